// round 1
// baseline (speedup 1.0000x reference)
#include <cuda_runtime.h>

#define BATCH 512
#define SEQL  1000
#define HID   128
#define G4    512   // 4*HID
#define NB    4     // batch elements per CTA
#define NCTA  128   // NCTA * NB == BATCH
#define NT    512   // threads per CTA (one per gate row)

__device__ __forceinline__ float sigf(float x) { return 1.0f / (1.0f + __expf(-x)); }

__global__ __launch_bounds__(NT, 1)
void lstm_persistent_kernel(const float* __restrict__ x,
                            const float* __restrict__ w_ih1,
                            const float* __restrict__ w_hh1,
                            const float* __restrict__ b_ih1,
                            const float* __restrict__ b_hh1,
                            const float* __restrict__ w_ih2,
                            const float* __restrict__ w_hh2,
                            const float* __restrict__ b_ih2,
                            const float* __restrict__ b_hh2,
                            const float* __restrict__ w_lin,
                            const float* __restrict__ b_lin,
                            float* __restrict__ out)
{
    __shared__ __align__(16) float xbuf[NB * SEQL];   // 16 KB: this CTA's x rows
    __shared__ __align__(16) float h1s[NB][HID];
    __shared__ __align__(16) float c1s[NB][HID];
    __shared__ __align__(16) float h2s[NB][HID];
    __shared__ __align__(16) float c2s[NB][HID];
    __shared__ __align__(16) float gbuf[NB][G4];      // 8 KB, reused by both layers
    __shared__ __align__(16) float wlin_s[HID];
    __shared__ float outw[NT / 32];

    const int g  = threadIdx.x;          // gate row index 0..511
    const int b0 = blockIdx.x * NB;      // first batch element of this CTA

    // Preload x rows (rows b0..b0+3 are contiguous in [B, L] row-major)
    for (int idx = g; idx < NB * SEQL; idx += NT)
        xbuf[idx] = x[b0 * SEQL + idx];

    if (g < HID) wlin_s[g] = w_lin[g];

    // Zero initial state
    for (int idx = g; idx < NB * HID; idx += NT) {
        (&h1s[0][0])[idx] = 0.0f;
        (&c1s[0][0])[idx] = 0.0f;
        (&h2s[0][0])[idx] = 0.0f;
        (&c2s[0][0])[idx] = 0.0f;
    }

    const float bias1 = b_ih1[g] + b_hh1[g];
    const float bias2 = b_ih2[g] + b_hh2[g];
    const float wi1   = w_ih1[g];        // w_ih1 is [4H, 1]
    const float blin  = b_lin[0];

    const float4* wr1 = reinterpret_cast<const float4*>(w_hh1 + g * HID);
    const float4* wi2 = reinterpret_cast<const float4*>(w_ih2 + g * HID);
    const float4* wr2 = reinterpret_cast<const float4*>(w_hh2 + g * HID);

    const int bb = g >> 7;               // which batch (0..3) this thread updates
    const int uu = g & 127;              // which hidden unit

    __syncthreads();

    for (int t = 0; t < SEQL; t++) {
        // ---------------- Layer 1 gates: g1[b][g] = bias1 + wi1*x[b,t] + w_hh1[g,:]·h1[b,:]
        float a0 = fmaf(wi1, xbuf[0 * SEQL + t], bias1);
        float a1 = fmaf(wi1, xbuf[1 * SEQL + t], bias1);
        float a2 = fmaf(wi1, xbuf[2 * SEQL + t], bias1);
        float a3 = fmaf(wi1, xbuf[3 * SEQL + t], bias1);
        #pragma unroll 8
        for (int kk = 0; kk < HID / 4; kk++) {
            float4 w  = __ldg(wr1 + kk);
            float4 h0 = *reinterpret_cast<const float4*>(&h1s[0][kk * 4]);
            float4 h1 = *reinterpret_cast<const float4*>(&h1s[1][kk * 4]);
            float4 h2 = *reinterpret_cast<const float4*>(&h1s[2][kk * 4]);
            float4 h3 = *reinterpret_cast<const float4*>(&h1s[3][kk * 4]);
            a0 = fmaf(w.x, h0.x, fmaf(w.y, h0.y, fmaf(w.z, h0.z, fmaf(w.w, h0.w, a0))));
            a1 = fmaf(w.x, h1.x, fmaf(w.y, h1.y, fmaf(w.z, h1.z, fmaf(w.w, h1.w, a1))));
            a2 = fmaf(w.x, h2.x, fmaf(w.y, h2.y, fmaf(w.z, h2.z, fmaf(w.w, h2.w, a2))));
            a3 = fmaf(w.x, h3.x, fmaf(w.y, h3.y, fmaf(w.z, h3.z, fmaf(w.w, h3.w, a3))));
        }
        gbuf[0][g] = a0; gbuf[1][g] = a1; gbuf[2][g] = a2; gbuf[3][g] = a3;
        __syncthreads();

        // ---------------- Layer 1 elementwise update (thread -> one (batch, unit))
        {
            float gi = sigf(gbuf[bb][uu]);
            float gf = sigf(gbuf[bb][128 + uu]);
            float gg = tanhf(gbuf[bb][256 + uu]);
            float go = sigf(gbuf[bb][384 + uu]);
            float c  = fmaf(gf, c1s[bb][uu], gi * gg);
            c1s[bb][uu] = c;
            h1s[bb][uu] = go * tanhf(c);
        }
        __syncthreads();

        // ---------------- Layer 2 gates: bias2 + w_ih2[g,:]·h1[b,:] + w_hh2[g,:]·h2[b,:]
        a0 = bias2; a1 = bias2; a2 = bias2; a3 = bias2;
        #pragma unroll 4
        for (int kk = 0; kk < HID / 4; kk++) {
            float4 wa = __ldg(wi2 + kk);
            float4 wb = __ldg(wr2 + kk);
            float4 p0 = *reinterpret_cast<const float4*>(&h1s[0][kk * 4]);
            float4 p1 = *reinterpret_cast<const float4*>(&h1s[1][kk * 4]);
            float4 p2 = *reinterpret_cast<const float4*>(&h1s[2][kk * 4]);
            float4 p3 = *reinterpret_cast<const float4*>(&h1s[3][kk * 4]);
            float4 q0 = *reinterpret_cast<const float4*>(&h2s[0][kk * 4]);
            float4 q1 = *reinterpret_cast<const float4*>(&h2s[1][kk * 4]);
            float4 q2 = *reinterpret_cast<const float4*>(&h2s[2][kk * 4]);
            float4 q3 = *reinterpret_cast<const float4*>(&h2s[3][kk * 4]);
            a0 = fmaf(wa.x, p0.x, fmaf(wa.y, p0.y, fmaf(wa.z, p0.z, fmaf(wa.w, p0.w, a0))));
            a1 = fmaf(wa.x, p1.x, fmaf(wa.y, p1.y, fmaf(wa.z, p1.z, fmaf(wa.w, p1.w, a1))));
            a2 = fmaf(wa.x, p2.x, fmaf(wa.y, p2.y, fmaf(wa.z, p2.z, fmaf(wa.w, p2.w, a2))));
            a3 = fmaf(wa.x, p3.x, fmaf(wa.y, p3.y, fmaf(wa.z, p3.z, fmaf(wa.w, p3.w, a3))));
            a0 = fmaf(wb.x, q0.x, fmaf(wb.y, q0.y, fmaf(wb.z, q0.z, fmaf(wb.w, q0.w, a0))));
            a1 = fmaf(wb.x, q1.x, fmaf(wb.y, q1.y, fmaf(wb.z, q1.z, fmaf(wb.w, q1.w, a1))));
            a2 = fmaf(wb.x, q2.x, fmaf(wb.y, q2.y, fmaf(wb.z, q2.z, fmaf(wb.w, q2.w, a2))));
            a3 = fmaf(wb.x, q3.x, fmaf(wb.y, q3.y, fmaf(wb.z, q3.z, fmaf(wb.w, q3.w, a3))));
        }
        gbuf[0][g] = a0; gbuf[1][g] = a1; gbuf[2][g] = a2; gbuf[3][g] = a3;
        __syncthreads();

        // ---------------- Layer 2 elementwise update + output partial
        float hval;
        {
            float gi = sigf(gbuf[bb][uu]);
            float gf = sigf(gbuf[bb][128 + uu]);
            float gg = tanhf(gbuf[bb][256 + uu]);
            float go = sigf(gbuf[bb][384 + uu]);
            float c  = fmaf(gf, c2s[bb][uu], gi * gg);
            c2s[bb][uu] = c;
            hval = go * tanhf(c);
            h2s[bb][uu] = hval;
        }
        // out[b, t] = w_lin · h2_new[b] + b_lin  (warp reduce; warps 4b..4b+3 cover batch b)
        float p = wlin_s[uu] * hval;
        #pragma unroll
        for (int off = 16; off; off >>= 1)
            p += __shfl_down_sync(0xffffffffu, p, off);
        if ((g & 31) == 0) outw[g >> 5] = p;
        __syncthreads();
        if (g < NB) {
            float o4 = outw[4 * g] + outw[4 * g + 1] + outw[4 * g + 2] + outw[4 * g + 3] + blin;
            out[(b0 + g) * SEQL + t] = o4;
        }
    }
}

extern "C" void kernel_launch(void* const* d_in, const int* in_sizes, int n_in,
                              void* d_out, int out_size)
{
    const float* x     = (const float*)d_in[0];
    const float* w_ih1 = (const float*)d_in[1];
    const float* w_hh1 = (const float*)d_in[2];
    const float* b_ih1 = (const float*)d_in[3];
    const float* b_hh1 = (const float*)d_in[4];
    const float* w_ih2 = (const float*)d_in[5];
    const float* w_hh2 = (const float*)d_in[6];
    const float* b_ih2 = (const float*)d_in[7];
    const float* b_hh2 = (const float*)d_in[8];
    const float* w_lin = (const float*)d_in[9];
    const float* b_lin = (const float*)d_in[10];
    float* out = (float*)d_out;

    lstm_persistent_kernel<<<NCTA, NT>>>(x, w_ih1, w_hh1, b_ih1, b_hh1,
                                         w_ih2, w_hh2, b_ih2, b_hh2,
                                         w_lin, b_lin, out);
}

// round 2
// speedup vs baseline: 3.7750x; 3.7750x over previous
#include <cuda_runtime.h>
#include <cuda_fp16.h>

#define BATCH 512
#define SEQL  1000
#define HID   128
#define G4    512   // 4*HID gate rows
#define NB    4     // batch elements per CTA
#define NCTA  128
#define NT    512

// Transposed fp16 weights: [k_chunk][gate_row][8 k-values] -> warp reads 512B contiguous
__device__ __half g_w1t[16][G4][8];   // w_hh1   (k = 0..127)
__device__ __half g_w2t[32][G4][8];   // [w_ih2 | w_hh2] concatenated over k = 0..255

__global__ void setup_weights(const float* __restrict__ w_hh1,
                              const float* __restrict__ w_ih2,
                              const float* __restrict__ w_hh2)
{
    int idx = blockIdx.x * 256 + threadIdx.x;     // 512*384 total
    if (idx >= G4 * 384) return;
    int g = idx / 384;
    int k = idx % 384;
    if (k < 128) {
        g_w1t[k >> 3][g][k & 7] = __float2half_rn(w_hh1[g * 128 + k]);
    } else {
        int kk = k - 128;
        float v = (kk < 128) ? w_ih2[g * 128 + kk] : w_hh2[g * 128 + (kk - 128)];
        g_w2t[kk >> 3][g][kk & 7] = __float2half_rn(v);
    }
}

typedef unsigned long long ull;

__device__ __forceinline__ ull pk2(float lo, float hi) {
    ull r; asm("mov.b64 %0, {%1, %2};" : "=l"(r) : "f"(lo), "f"(hi)); return r;
}
__device__ __forceinline__ ull dup2(float v) { return pk2(v, v); }
__device__ __forceinline__ float2 unpk(ull v) {
    float2 r; asm("mov.b64 {%0, %1}, %2;" : "=f"(r.x), "=f"(r.y) : "l"(v)); return r;
}
__device__ __forceinline__ ull fma2(ull a, ull b, ull c) {
    ull d; asm("fma.rn.f32x2 %0, %1, %2, %3;" : "=l"(d) : "l"(a), "l"(b), "l"(c)); return d;
}

__device__ __forceinline__ float sigf(float x) {
    return __fdividef(1.0f, 1.0f + __expf(-x));
}
__device__ __forceinline__ float tanhfast(float x) {
    x = fminf(fmaxf(x, -15.0f), 15.0f);          // keep __expf finite
    float e = __expf(-2.0f * x);
    return __fdividef(1.0f - e, 1.0f + e);
}

__global__ __launch_bounds__(NT, 1)
void lstm_persistent_kernel(const float* __restrict__ x,
                            const float* __restrict__ w_ih1,
                            const float* __restrict__ b_ih1,
                            const float* __restrict__ b_hh1,
                            const float* __restrict__ b_ih2,
                            const float* __restrict__ b_hh2,
                            const float* __restrict__ w_lin,
                            const float* __restrict__ b_lin,
                            float* __restrict__ out)
{
    __shared__ __align__(16) float xbuf[NB * SEQL];     // 16 KB
    __shared__ __align__(16) float hcat[256][NB];       // [h1(0..127) | h2(128..255)] batch-packed, 4 KB
    __shared__ __align__(16) float gbuf[NB][G4];        // 8 KB
    __shared__ float wlin_s[HID];
    __shared__ float outw[NT / 32];

    const int g  = threadIdx.x;
    const int b0 = blockIdx.x * NB;
    const int bb = g >> 7;
    const int uu = g & 127;

    for (int idx = g; idx < NB * SEQL; idx += NT)
        xbuf[idx] = x[b0 * SEQL + idx];
    if (g < HID) wlin_s[g] = w_lin[g];
    for (int idx = g; idx < 256 * NB; idx += NT)
        (&hcat[0][0])[idx] = 0.0f;

    const float bias1 = b_ih1[g] + b_hh1[g];
    const float bias2 = b_ih2[g] + b_hh2[g];
    const float wi1   = w_ih1[g];
    const float blin  = b_lin[0];

    float c1r = 0.0f, c2r = 0.0f;    // this thread's (bb,uu) cell states

    __syncthreads();

    for (int t = 0; t < SEQL; t++) {
        // ============ Layer 1 gates: bias1 + wi1*x[b,t] + w_hh1[g,:]·h1[b,:]
        float x0 = xbuf[0 * SEQL + t], x1 = xbuf[1 * SEQL + t];
        float x2 = xbuf[2 * SEQL + t], x3 = xbuf[3 * SEQL + t];
        ull acc01 = pk2(fmaf(wi1, x0, bias1), fmaf(wi1, x1, bias1));
        ull acc23 = pk2(fmaf(wi1, x2, bias1), fmaf(wi1, x3, bias1));

        #pragma unroll
        for (int k8 = 0; k8 < 16; k8++) {
            uint4 wv = *reinterpret_cast<const uint4*>(&g_w1t[k8][g][0]);
            const __half2* wh = reinterpret_cast<const __half2*>(&wv);
            #pragma unroll
            for (int j = 0; j < 4; j++) {
                float2 wf = __half22float2(wh[j]);
                int k = k8 * 8 + j * 2;
                ulonglong2 ha = *reinterpret_cast<const ulonglong2*>(&hcat[k][0]);
                ulonglong2 hb = *reinterpret_cast<const ulonglong2*>(&hcat[k + 1][0]);
                ull wx = dup2(wf.x), wy = dup2(wf.y);
                acc01 = fma2(wx, ha.x, acc01); acc23 = fma2(wx, ha.y, acc23);
                acc01 = fma2(wy, hb.x, acc01); acc23 = fma2(wy, hb.y, acc23);
            }
        }
        { float2 u = unpk(acc01), v = unpk(acc23);
          gbuf[0][g] = u.x; gbuf[1][g] = u.y; gbuf[2][g] = v.x; gbuf[3][g] = v.y; }
        __syncthreads();

        // ============ Layer 1 elementwise (thread -> one (batch, unit))
        {
            float gi = sigf(gbuf[bb][uu]);
            float gf = sigf(gbuf[bb][128 + uu]);
            float gg = tanhfast(gbuf[bb][256 + uu]);
            float go = sigf(gbuf[bb][384 + uu]);
            c1r = fmaf(gf, c1r, gi * gg);
            hcat[uu][bb] = go * tanhfast(c1r);
        }
        __syncthreads();

        // ============ Layer 2 gates: bias2 + [w_ih2|w_hh2][g,:]·[h1|h2][b,:]
        acc01 = dup2(bias2); acc23 = dup2(bias2);
        #pragma unroll 8
        for (int k8 = 0; k8 < 32; k8++) {
            uint4 wv = *reinterpret_cast<const uint4*>(&g_w2t[k8][g][0]);
            const __half2* wh = reinterpret_cast<const __half2*>(&wv);
            #pragma unroll
            for (int j = 0; j < 4; j++) {
                float2 wf = __half22float2(wh[j]);
                int k = k8 * 8 + j * 2;
                ulonglong2 ha = *reinterpret_cast<const ulonglong2*>(&hcat[k][0]);
                ulonglong2 hb = *reinterpret_cast<const ulonglong2*>(&hcat[k + 1][0]);
                ull wx = dup2(wf.x), wy = dup2(wf.y);
                acc01 = fma2(wx, ha.x, acc01); acc23 = fma2(wx, ha.y, acc23);
                acc01 = fma2(wy, hb.x, acc01); acc23 = fma2(wy, hb.y, acc23);
            }
        }
        { float2 u = unpk(acc01), v = unpk(acc23);
          gbuf[0][g] = u.x; gbuf[1][g] = u.y; gbuf[2][g] = v.x; gbuf[3][g] = v.y; }
        __syncthreads();

        // ============ Layer 2 elementwise + output partial
        float h2v;
        {
            float gi = sigf(gbuf[bb][uu]);
            float gf = sigf(gbuf[bb][128 + uu]);
            float gg = tanhfast(gbuf[bb][256 + uu]);
            float go = sigf(gbuf[bb][384 + uu]);
            c2r = fmaf(gf, c2r, gi * gg);
            h2v = go * tanhfast(c2r);
            hcat[128 + uu][bb] = h2v;
        }
        float p = wlin_s[uu] * h2v;
        #pragma unroll
        for (int off = 16; off; off >>= 1)
            p += __shfl_down_sync(0xffffffffu, p, off);
        if ((g & 31) == 0) outw[g >> 5] = p;
        __syncthreads();
        if (g < NB) {
            float o4 = outw[4 * g] + outw[4 * g + 1] + outw[4 * g + 2] + outw[4 * g + 3] + blin;
            out[(b0 + g) * SEQL + t] = o4;
        }
    }
}

extern "C" void kernel_launch(void* const* d_in, const int* in_sizes, int n_in,
                              void* d_out, int out_size)
{
    const float* x     = (const float*)d_in[0];
    const float* w_ih1 = (const float*)d_in[1];
    const float* w_hh1 = (const float*)d_in[2];
    const float* b_ih1 = (const float*)d_in[3];
    const float* b_hh1 = (const float*)d_in[4];
    const float* w_ih2 = (const float*)d_in[5];
    const float* w_hh2 = (const float*)d_in[6];
    const float* b_ih2 = (const float*)d_in[7];
    const float* b_hh2 = (const float*)d_in[8];
    const float* w_lin = (const float*)d_in[9];
    const float* b_lin = (const float*)d_in[10];
    float* out = (float*)d_out;

    setup_weights<<<(G4 * 384 + 255) / 256, 256>>>(w_hh1, w_ih2, w_hh2);
    lstm_persistent_kernel<<<NCTA, NT>>>(x, w_ih1, b_ih1, b_hh1,
                                         b_ih2, b_hh2, w_lin, b_lin, out);
}

// round 5
// speedup vs baseline: 14.1559x; 3.7499x over previous
#include <cuda_runtime.h>
#include <cuda_fp16.h>

typedef unsigned int u32;
typedef unsigned short u16;

#define SEQL 1000
#define CL   4
#define NT   256
#define GRID 128
#define NBC  16

// ---- smem layout (bytes). hcat rows padded to 528B for conflict-free frag LDS.
#define HROW 528
#define HBUF (16 * HROW)                     // one h buffer: 16 n-rows
#define OFF_HCAT 0u                          // [2][16][HROW]  fp16 k-major rows
#define OFF_GST  (2u * HBUF)                 // [16 n][132 f32] gate staging
#define GROWW 132
#define OFF_X    (OFF_GST + 16u * GROWW * 4u)       // [16][1000] f32
#define OFF_WP   (OFF_X + 16u * SEQL * 4u)          // [8 warps][16] f32
#define OFF_OACC (OFF_WP + 8u * 16u * 4u)           // [4 ranks][16] f32
#define SMEM_TOTAL (OFF_OACC + 4u * 16u * 4u + 16u)

static __device__ __forceinline__ u32 s2u(const void* p) {
    u32 a; asm("{ .reg .u64 t; cvta.to.shared.u64 t, %1; cvt.u32.u64 %0, t; }" : "=r"(a) : "l"(p));
    return a;
}
static __device__ __forceinline__ u32 mapa_rk(u32 addr, u32 rk) {
    u32 r; asm("mapa.shared::cluster.u32 %0, %1, %2;" : "=r"(r) : "r"(addr), "r"(rk));
    return r;
}
static __device__ __forceinline__ void stc_u16(u32 a, u16 v) {
    asm volatile("st.shared::cluster.u16 [%0], %1;" :: "r"(a), "h"(v) : "memory");
}
static __device__ __forceinline__ void stc_u32(u32 a, u32 v) {
    asm volatile("st.shared::cluster.u32 [%0], %1;" :: "r"(a), "r"(v) : "memory");
}
#define CSYNC() do { asm volatile("barrier.cluster.arrive.aligned;" ::: "memory"); \
                     asm volatile("barrier.cluster.wait.aligned;" ::: "memory"); } while (0)

static __device__ __forceinline__ void mma16816(float* d, const u32* a, u32 b0, u32 b1) {
    asm volatile("mma.sync.aligned.m16n8k16.row.col.f32.f16.f16.f32 "
        "{%0,%1,%2,%3}, {%4,%5,%6,%7}, {%8,%9}, {%0,%1,%2,%3};"
        : "+f"(d[0]), "+f"(d[1]), "+f"(d[2]), "+f"(d[3])
        : "r"(a[0]), "r"(a[1]), "r"(a[2]), "r"(a[3]), "r"(b0), "r"(b1));
}

static __device__ __forceinline__ float sigf(float x) {
    return __fdividef(1.0f, 1.0f + __expf(-x));
}
static __device__ __forceinline__ float tanhfast(float x) {
    x = fminf(fmaxf(x, -15.0f), 15.0f);
    float e = __expf(-2.0f * x);
    return __fdividef(1.0f - e, 1.0f + e);
}
static __device__ __forceinline__ u32 f2h2(float lo, float hi) {
    __half2 h = __floats2half2_rn(lo, hi);
    return *reinterpret_cast<u32*>(&h);
}

__global__ __launch_bounds__(NT, 1) __cluster_dims__(CL, 1, 1)
void lstm_mma_kernel(const float* __restrict__ x,
                     const float* __restrict__ w_ih1,
                     const float* __restrict__ w_hh1,
                     const float* __restrict__ b_ih1,
                     const float* __restrict__ b_hh1,
                     const float* __restrict__ w_ih2,
                     const float* __restrict__ w_hh2,
                     const float* __restrict__ b_ih2,
                     const float* __restrict__ b_hh2,
                     const float* __restrict__ w_lin,
                     const float* __restrict__ b_lin,
                     float* __restrict__ out)
{
    extern __shared__ __align__(16) char smem[];
    const u32 sb = s2u(smem);
    const int tid  = threadIdx.x;
    const int lane = tid & 31;
    const int w    = tid >> 5;           // warp 0..7 -> M-tile w (rows 16w..16w+15)
    u32 rank; asm("mov.u32 %0, %%cluster_ctarank;" : "=r"(rank));
    const int b0 = (blockIdx.x >> 2) * NBC;

    const int fg = lane >> 2;            // frag row/col group 0..7
    const int ft = lane & 3;             // frag quad 0..3

    // ---------- build A fragments in registers (weights fp16, loaded once)
    // local row r (0..127): gate = r>>5, u = r&31; global gate row G = gate*128 + rank*32 + u
    const int r0 = w * 16 + fg;
    const int r1 = r0 + 8;
    const int G0 = (r0 >> 5) * 128 + (int)rank * 32 + (r0 & 31);
    const int G1 = (r1 >> 5) * 128 + (int)rank * 32 + (r1 & 31);

    u32 A1[8][4], A2[16][4];
    #pragma unroll
    for (int kt = 0; kt < 8; kt++) {
        int k = kt * 16 + 2 * ft;
        A1[kt][0] = f2h2(w_hh1[G0 * 128 + k],     w_hh1[G0 * 128 + k + 1]);
        A1[kt][1] = f2h2(w_hh1[G1 * 128 + k],     w_hh1[G1 * 128 + k + 1]);
        A1[kt][2] = f2h2(w_hh1[G0 * 128 + k + 8], w_hh1[G0 * 128 + k + 9]);
        A1[kt][3] = f2h2(w_hh1[G1 * 128 + k + 8], w_hh1[G1 * 128 + k + 9]);
    }
    #pragma unroll
    for (int kt = 0; kt < 16; kt++) {
        int k = kt * 16 + 2 * ft;
        const float* Wa = (k < 128) ? (w_ih2 + k)       : (w_hh2 + k - 128);
        const float* Wb = (k + 8 < 128) ? (w_ih2 + k + 8) : (w_hh2 + k + 8 - 128);
        A2[kt][0] = f2h2(Wa[G0 * 128],     Wa[G0 * 128 + 1]);
        A2[kt][1] = f2h2(Wa[G1 * 128],     Wa[G1 * 128 + 1]);
        A2[kt][2] = f2h2(Wb[G0 * 128],     Wb[G0 * 128 + 1]);
        A2[kt][3] = f2h2(Wb[G1 * 128],     Wb[G1 * 128 + 1]);
    }

    // ---------- init smem: zero hcat (both buffers incl. padding), load x slab
    for (u32 i = (u32)tid; i < 2u * HBUF / 4u; i += NT)
        ((u32*)smem)[i] = 0u;
    float* xsh = (float*)(smem + OFF_X);
    for (int i = tid; i < NBC * SEQL; i += NT)
        xsh[i] = x[b0 * SEQL + i];

    // ---------- elementwise constants: thread -> unit ue (0..31), batches be, be+8
    const int ue = tid >> 3;
    const int be = tid & 7;
    float wi1g[4], b1g[4], b2g[4];
    #pragma unroll
    for (int gate = 0; gate < 4; gate++) {
        int G = gate * 128 + (int)rank * 32 + ue;
        wi1g[gate] = w_ih1[G];
        b1g[gate]  = b_ih1[G] + b_hh1[G];
        b2g[gate]  = b_ih2[G] + b_hh2[G];
    }
    const float wlu  = w_lin[(int)rank * 32 + ue];
    const float blin = b_lin[0];
    float c1[2] = {0.f, 0.f}, c2[2] = {0.f, 0.f};

    // remote bases for h exchange + rank0 output accumulator
    u32 rb[CL];
    #pragma unroll
    for (u32 rk = 0; rk < CL; rk++) rb[rk] = mapa_rk(sb + OFF_HCAT, rk);
    const u32 oacc0 = mapa_rk(sb + OFF_OACC, 0);

    float* gst   = (float*)(smem + OFF_GST);
    float* wpart = (float*)(smem + OFF_WP);
    float* oacc  = (float*)(smem + OFF_OACC);

    __syncthreads();
    CSYNC();   // zeros + x visible; all CTAs ready

    for (int t = 0; t < SEQL; t++) {
        const u32 pA = (u32)((t + 1) & 1);   // layer1 B source; h2 write target
        const u32 pB = (u32)(t & 1);         // h1 write target; layer2 B source

        // ================= window A : layer 1 =================
        {
            const u32* hp = (const u32*)(smem + OFF_HCAT + pA * HBUF);
            float d0[4] = {0.f, 0.f, 0.f, 0.f};
            float d1[4] = {0.f, 0.f, 0.f, 0.f};
            #pragma unroll
            for (int kt = 0; kt < 8; kt++) {
                int ko = kt * 8 + ft;                 // u32 index of (k=16kt+2ft)
                u32 bA0 = hp[fg * 132 + ko];          // n = fg        (HROW/4 = 132)
                u32 bA1 = hp[fg * 132 + ko + 4];      // k+8
                u32 bB0 = hp[(8 + fg) * 132 + ko];    // n = 8+fg
                u32 bB1 = hp[(8 + fg) * 132 + ko + 4];
                mma16816(d0, A1[kt], bA0, bA1);
                mma16816(d1, A1[kt], bB0, bB1);
            }
            // stage: gst[n][row], row-padded 132
            int rr = w * 16 + fg;
            gst[(2 * ft)     * GROWW + rr]     = d0[0];
            gst[(2 * ft + 1) * GROWW + rr]     = d0[1];
            gst[(2 * ft)     * GROWW + rr + 8] = d0[2];
            gst[(2 * ft + 1) * GROWW + rr + 8] = d0[3];
            gst[(8 + 2 * ft)     * GROWW + rr]     = d1[0];
            gst[(8 + 2 * ft + 1) * GROWW + rr]     = d1[1];
            gst[(8 + 2 * ft)     * GROWW + rr + 8] = d1[2];
            gst[(8 + 2 * ft + 1) * GROWW + rr + 8] = d1[3];
        }
        __syncthreads();

        // elementwise layer 1 + h1 exchange to all 4 ranks
        #pragma unroll
        for (int j = 0; j < 2; j++) {
            int b = be + 8 * j;
            float xi = xsh[b * SEQL + t];
            float vi = gst[b * GROWW + ue]      + fmaf(wi1g[0], xi, b1g[0]);
            float vf = gst[b * GROWW + 32 + ue] + fmaf(wi1g[1], xi, b1g[1]);
            float vg = gst[b * GROWW + 64 + ue] + fmaf(wi1g[2], xi, b1g[2]);
            float vo = gst[b * GROWW + 96 + ue] + fmaf(wi1g[3], xi, b1g[3]);
            float gi = sigf(vi), gf = sigf(vf), gg = tanhfast(vg), go = sigf(vo);
            c1[j] = fmaf(gf, c1[j], gi * gg);
            u16 hv = __half_as_ushort(__float2half_rn(go * tanhfast(c1[j])));
            u32 off = pB * HBUF + (u32)b * HROW + ((u32)rank * 32u + (u32)ue) * 2u;
            stc_u16(rb[0] + off, hv); stc_u16(rb[1] + off, hv);
            stc_u16(rb[2] + off, hv); stc_u16(rb[3] + off, hv);
        }
        CSYNC();

        // ================= window B : layer 2 =================
        {
            const u32* hp = (const u32*)(smem + OFF_HCAT + pB * HBUF);
            float d0[4] = {0.f, 0.f, 0.f, 0.f};
            float d1[4] = {0.f, 0.f, 0.f, 0.f};
            #pragma unroll
            for (int kt = 0; kt < 16; kt++) {
                int ko = kt * 8 + ft;
                u32 bA0 = hp[fg * 132 + ko];
                u32 bA1 = hp[fg * 132 + ko + 4];
                u32 bB0 = hp[(8 + fg) * 132 + ko];
                u32 bB1 = hp[(8 + fg) * 132 + ko + 4];
                mma16816(d0, A2[kt], bA0, bA1);
                mma16816(d1, A2[kt], bB0, bB1);
            }
            int rr = w * 16 + fg;
            gst[(2 * ft)     * GROWW + rr]     = d0[0];
            gst[(2 * ft + 1) * GROWW + rr]     = d0[1];
            gst[(2 * ft)     * GROWW + rr + 8] = d0[2];
            gst[(2 * ft + 1) * GROWW + rr + 8] = d0[3];
            gst[(8 + 2 * ft)     * GROWW + rr]     = d1[0];
            gst[(8 + 2 * ft + 1) * GROWW + rr]     = d1[1];
            gst[(8 + 2 * ft)     * GROWW + rr + 8] = d1[2];
            gst[(8 + 2 * ft + 1) * GROWW + rr + 8] = d1[3];
        }
        __syncthreads();

        // elementwise layer 2 + h2 exchange + output partial
        float p[2];
        #pragma unroll
        for (int j = 0; j < 2; j++) {
            int b = be + 8 * j;
            float vi = gst[b * GROWW + ue]      + b2g[0];
            float vf = gst[b * GROWW + 32 + ue] + b2g[1];
            float vg = gst[b * GROWW + 64 + ue] + b2g[2];
            float vo = gst[b * GROWW + 96 + ue] + b2g[3];
            float gi = sigf(vi), gf = sigf(vf), gg = tanhfast(vg), go = sigf(vo);
            c2[j] = fmaf(gf, c2[j], gi * gg);
            float h2v = go * tanhfast(c2[j]);
            u16 hv = __half_as_ushort(__float2half_rn(h2v));
            u32 off = pA * HBUF + (u32)b * HROW + (128u + (u32)rank * 32u + (u32)ue) * 2u;
            stc_u16(rb[0] + off, hv); stc_u16(rb[1] + off, hv);
            stc_u16(rb[2] + off, hv); stc_u16(rb[3] + off, hv);
            p[j] = wlu * h2v;
        }
        // reduce over the 4 units this warp covers (lane>>3 = local u)
        #pragma unroll
        for (int j = 0; j < 2; j++) {
            p[j] += __shfl_xor_sync(0xffffffffu, p[j], 8);
            p[j] += __shfl_xor_sync(0xffffffffu, p[j], 16);
        }
        if (lane < 8) { wpart[w * 16 + lane] = p[0]; wpart[w * 16 + lane + 8] = p[1]; }
        __syncthreads();
        if (tid < 16) {
            float s = 0.f;
            #pragma unroll
            for (int ww = 0; ww < 8; ww++) s += wpart[ww * 16 + tid];
            stc_u32(oacc0 + ((u32)rank * 16u + (u32)tid) * 4u, __float_as_uint(s));
        }
        CSYNC();

        // rank 0 writes out[b, t] (reads oacc written before the csync above;
        // next oacc write is after the NEXT mid-step csync -> race-free)
        if (rank == 0 && tid < 16) {
            float o = oacc[tid] + oacc[16 + tid] + oacc[32 + tid] + oacc[48 + tid] + blin;
            out[(b0 + tid) * SEQL + t] = o;
        }
    }
}

extern "C" void kernel_launch(void* const* d_in, const int* in_sizes, int n_in,
                              void* d_out, int out_size)
{
    static int init = 0;
    if (!init) {
        cudaFuncSetAttribute(lstm_mma_kernel, cudaFuncAttributeMaxDynamicSharedMemorySize, SMEM_TOTAL);
        init = 1;
    }
    lstm_mma_kernel<<<GRID, NT, SMEM_TOTAL>>>(
        (const float*)d_in[0], (const float*)d_in[1], (const float*)d_in[2],
        (const float*)d_in[3], (const float*)d_in[4], (const float*)d_in[5],
        (const float*)d_in[6], (const float*)d_in[7], (const float*)d_in[8],
        (const float*)d_in[9], (const float*)d_in[10], (float*)d_out);
}

// round 6
// speedup vs baseline: 24.1587x; 1.7066x over previous
#include <cuda_runtime.h>
#include <cuda_fp16.h>

typedef unsigned int u32;
typedef unsigned short u16;

#define SEQL 1000
#define CL   4
#define NT   256
#define GRID 128
#define NBC  16

// smem layout
#define HROW 528
#define HR4  132
#define HBUF (16 * HROW)                      // one hcat buffer (16 batches x 256k fp16 + pad)
#define GROW 260                              // gst row stride (f32 words)
#define OFF_HCAT 0u
#define OFF_GST  (2u * HBUF)                  // [16 batch][260] f32 ; rows 0-127 L2 gates, 128-255 L1 gates
#define OFF_X    (OFF_GST + 16u * GROW * 4u)  // [16][1000] f32
#define OFF_WLIN (OFF_X + 16u * SEQL * 4u)    // [128] f32
#define SMEM_TOTAL (OFF_WLIN + 512u + 16u)

static __device__ __forceinline__ u32 s2u(const void* p) {
    u32 a; asm("{ .reg .u64 t; cvta.to.shared.u64 t, %1; cvt.u32.u64 %0, t; }" : "=r"(a) : "l"(p));
    return a;
}
static __device__ __forceinline__ u32 mapa_rk(u32 addr, u32 rk) {
    u32 r; asm("mapa.shared::cluster.u32 %0, %1, %2;" : "=r"(r) : "r"(addr), "r"(rk));
    return r;
}
static __device__ __forceinline__ void stc_u32(u32 a, u32 v) {
    asm volatile("st.shared::cluster.u32 [%0], %1;" :: "r"(a), "r"(v) : "memory");
}
#define CSYNC() do { asm volatile("barrier.cluster.arrive.aligned;" ::: "memory"); \
                     asm volatile("barrier.cluster.wait.aligned;" ::: "memory"); } while (0)

static __device__ __forceinline__ void mma16816(float* d, const u32* a, u32 b0, u32 b1) {
    asm volatile("mma.sync.aligned.m16n8k16.row.col.f32.f16.f16.f32 "
        "{%0,%1,%2,%3}, {%4,%5,%6,%7}, {%8,%9}, {%0,%1,%2,%3};"
        : "+f"(d[0]), "+f"(d[1]), "+f"(d[2]), "+f"(d[3])
        : "r"(a[0]), "r"(a[1]), "r"(a[2]), "r"(a[3]), "r"(b0), "r"(b1));
}
static __device__ __forceinline__ float tanha(float x) {
    float y; asm("tanh.approx.f32 %0, %1;" : "=f"(y) : "f"(x)); return y;
}
static __device__ __forceinline__ float siga(float x) {
    return fmaf(tanha(0.5f * x), 0.5f, 0.5f);
}
static __device__ __forceinline__ u32 f2h2(float lo, float hi) {
    __half2 h = __floats2half2_rn(lo, hi);
    return *reinterpret_cast<u32*>(&h);
}

__global__ __launch_bounds__(NT, 1) __cluster_dims__(CL, 1, 1)
void lstm_fused_kernel(const float* __restrict__ x,
                       const float* __restrict__ w_ih1,
                       const float* __restrict__ w_hh1,
                       const float* __restrict__ b_ih1,
                       const float* __restrict__ b_hh1,
                       const float* __restrict__ w_ih2,
                       const float* __restrict__ w_hh2,
                       const float* __restrict__ b_ih2,
                       const float* __restrict__ b_hh2,
                       const float* __restrict__ w_lin,
                       const float* __restrict__ b_lin,
                       float* __restrict__ out)
{
    extern __shared__ __align__(16) char smem[];
    const u32 sb = s2u(smem);
    const int tid  = threadIdx.x;
    const int lane = tid & 31;
    const int w    = tid >> 5;
    u32 rank; asm("mov.u32 %0, %%cluster_ctarank;" : "=r"(rank));
    const int b0 = (blockIdx.x >> 2) * NBC;

    const int fg = lane >> 2;
    const int ft = lane & 3;

    // ---------- A fragments (fp16 weights, registers, loaded once)
    const int r0 = w * 16 + fg;
    const int r1 = r0 + 8;
    const int G0 = (r0 >> 5) * 128 + (int)rank * 32 + (r0 & 31);
    const int G1 = (r1 >> 5) * 128 + (int)rank * 32 + (r1 & 31);

    u32 A1[8][4], A2[16][4];
    #pragma unroll
    for (int kt = 0; kt < 8; kt++) {
        int k = kt * 16 + 2 * ft;
        A1[kt][0] = f2h2(w_hh1[G0 * 128 + k],     w_hh1[G0 * 128 + k + 1]);
        A1[kt][1] = f2h2(w_hh1[G1 * 128 + k],     w_hh1[G1 * 128 + k + 1]);
        A1[kt][2] = f2h2(w_hh1[G0 * 128 + k + 8], w_hh1[G0 * 128 + k + 9]);
        A1[kt][3] = f2h2(w_hh1[G1 * 128 + k + 8], w_hh1[G1 * 128 + k + 9]);
    }
    #pragma unroll
    for (int kt = 0; kt < 16; kt++) {
        int k = kt * 16 + 2 * ft;
        const float* Wa = (k < 128)     ? (w_ih2 + k)     : (w_hh2 + k - 128);
        const float* Wb = (k + 8 < 128) ? (w_ih2 + k + 8) : (w_hh2 + k + 8 - 128);
        A2[kt][0] = f2h2(Wa[G0 * 128],     Wa[G0 * 128 + 1]);
        A2[kt][1] = f2h2(Wa[G1 * 128],     Wa[G1 * 128 + 1]);
        A2[kt][2] = f2h2(Wb[G0 * 128],     Wb[G0 * 128 + 1]);
        A2[kt][3] = f2h2(Wb[G1 * 128],     Wb[G1 * 128 + 1]);
    }

    // ---------- init smem
    for (u32 i = (u32)tid; i < 2u * HBUF / 4u; i += NT)
        ((u32*)smem)[i] = 0u;
    float* xsh = (float*)(smem + OFF_X);
    for (int i = tid; i < NBC * SEQL; i += NT)
        xsh[i] = x[b0 * SEQL + i];
    float* wlin_s = (float*)(smem + OFF_WLIN);
    if (tid < 128) wlin_s[tid] = w_lin[tid];

    // ---------- elementwise mapping: L (0=layer1, 1=layer2), unit pair up, batches bq, bq+8
    const int L  = tid >> 7;
    const int up = (tid >> 3) & 15;
    const int bq = tid & 7;
    float wiA[4], wiB[4], bsA[4], bsB[4];
    #pragma unroll
    for (int g = 0; g < 4; g++) {
        int GA = g * 128 + (int)rank * 32 + 2 * up;
        int GB = GA + 1;
        if (L == 0) {
            wiA[g] = w_ih1[GA];            wiB[g] = w_ih1[GB];
            bsA[g] = b_ih1[GA] + b_hh1[GA]; bsB[g] = b_ih1[GB] + b_hh1[GB];
        } else {
            wiA[g] = 0.f;                   wiB[g] = 0.f;
            bsA[g] = b_ih2[GA] + b_hh2[GA]; bsB[g] = b_ih2[GB] + b_hh2[GB];
        }
    }
    float cA[2] = {0.f, 0.f}, cB[2] = {0.f, 0.f};
    const float blin = b_lin[0];

    u32 rb[CL];
    #pragma unroll
    for (u32 rk = 0; rk < CL; rk++) rb[rk] = mapa_rk(sb + OFF_HCAT, rk);
    const u32 kbyte = (u32)((L ? 128 : 0) + (int)rank * 32 + 2 * up) * 2u;

    float* gst = (float*)(smem + OFF_GST);
    const int grow_base = L ? 0 : 128;    // gst row offset for this thread's layer

    __syncthreads();
    CSYNC();   // all CTAs zeroed their buffers

    // ---------- prologue: h1(0) from x(0) only (h1(-1)=0); write into buffer 0
    if (L == 0) {
        #pragma unroll
        for (int j = 0; j < 2; j++) {
            int b = bq + 8 * j;
            float xv = xsh[b * SEQL];
            float iA = siga(fmaf(wiA[0], xv, bsA[0]));
            float fA = siga(fmaf(wiA[1], xv, bsA[1]));
            float gA = tanha(fmaf(wiA[2], xv, bsA[2]));
            float oA = siga(fmaf(wiA[3], xv, bsA[3]));
            cA[j] = iA * gA;
            float hA = oA * tanha(cA[j]);
            float iB = siga(fmaf(wiB[0], xv, bsB[0]));
            float fB = siga(fmaf(wiB[1], xv, bsB[1]));
            float gB = tanha(fmaf(wiB[2], xv, bsB[2]));
            float oB = siga(fmaf(wiB[3], xv, bsB[3]));
            cB[j] = iB * gB;
            float hB = oB * tanha(cB[j]);
            u32 pk = f2h2(hA, hB);
            u32 off = (u32)b * HROW + kbyte;          // buffer 0
            stc_u32(rb[0] + off, pk); stc_u32(rb[1] + off, pk);
            stc_u32(rb[2] + off, pk); stc_u32(rb[3] + off, pk);
        }
    }
    CSYNC();

    for (int t = 0; t < SEQL; t++) {
        const u32 cur = (u32)(t & 1);
        const u32 nxt = cur ^ 1u;

        // ===== fused MMA: gates2(t) [rows 0-127] and gates1(t+1) [rows 128-255]
        {
            const u32* hp = (const u32*)(smem + OFF_HCAT + cur * HBUF);
            float d2a[4] = {0,0,0,0}, d2b[4] = {0,0,0,0};
            float d1a[4] = {0,0,0,0}, d1b[4] = {0,0,0,0};
            #pragma unroll
            for (int kt = 0; kt < 8; kt++) {
                int ko = kt * 8 + ft;
                u32 bA0 = hp[fg * HR4 + ko];
                u32 bA1 = hp[fg * HR4 + ko + 4];
                u32 bB0 = hp[(8 + fg) * HR4 + ko];
                u32 bB1 = hp[(8 + fg) * HR4 + ko + 4];
                mma16816(d2a, A2[kt], bA0, bA1);
                mma16816(d2b, A2[kt], bB0, bB1);
                mma16816(d1a, A1[kt], bA0, bA1);
                mma16816(d1b, A1[kt], bB0, bB1);
            }
            #pragma unroll
            for (int kt = 8; kt < 16; kt++) {
                int ko = kt * 8 + ft;
                u32 bA0 = hp[fg * HR4 + ko];
                u32 bA1 = hp[fg * HR4 + ko + 4];
                u32 bB0 = hp[(8 + fg) * HR4 + ko];
                u32 bB1 = hp[(8 + fg) * HR4 + ko + 4];
                mma16816(d2a, A2[kt], bA0, bA1);
                mma16816(d2b, A2[kt], bB0, bB1);
            }
            int rr = w * 16 + fg;
            gst[(2 * ft)     * GROW + rr]     = d2a[0];
            gst[(2 * ft + 1) * GROW + rr]     = d2a[1];
            gst[(2 * ft)     * GROW + rr + 8] = d2a[2];
            gst[(2 * ft + 1) * GROW + rr + 8] = d2a[3];
            gst[(8 + 2 * ft)     * GROW + rr]     = d2b[0];
            gst[(9 + 2 * ft)     * GROW + rr]     = d2b[1];
            gst[(8 + 2 * ft)     * GROW + rr + 8] = d2b[2];
            gst[(9 + 2 * ft)     * GROW + rr + 8] = d2b[3];
            gst[(2 * ft)     * GROW + 128 + rr]     = d1a[0];
            gst[(2 * ft + 1) * GROW + 128 + rr]     = d1a[1];
            gst[(2 * ft)     * GROW + 128 + rr + 8] = d1a[2];
            gst[(2 * ft + 1) * GROW + 128 + rr + 8] = d1a[3];
            gst[(8 + 2 * ft)     * GROW + 128 + rr]     = d1b[0];
            gst[(9 + 2 * ft)     * GROW + 128 + rr]     = d1b[1];
            gst[(8 + 2 * ft)     * GROW + 128 + rr + 8] = d1b[2];
            gst[(9 + 2 * ft)     * GROW + 128 + rr + 8] = d1b[3];
        }
        __syncthreads();

        // ===== fused elementwise: layer2 -> h2(t), layer1 -> h1(t+1)
        if (L == 1 || t < SEQL - 1) {
            #pragma unroll
            for (int j = 0; j < 2; j++) {
                int b = bq + 8 * j;
                float xv = (L == 0) ? xsh[b * SEQL + t + 1] : 0.f;
                const float* gr = gst + b * GROW + grow_base + 2 * up;
                float2 vI = *(const float2*)(gr);
                float2 vF = *(const float2*)(gr + 32);
                float2 vG = *(const float2*)(gr + 64);
                float2 vO = *(const float2*)(gr + 96);
                float iA = siga(vI.x + fmaf(wiA[0], xv, bsA[0]));
                float fA = siga(vF.x + fmaf(wiA[1], xv, bsA[1]));
                float gA = tanha(vG.x + fmaf(wiA[2], xv, bsA[2]));
                float oA = siga(vO.x + fmaf(wiA[3], xv, bsA[3]));
                cA[j] = fmaf(fA, cA[j], iA * gA);
                float hA = oA * tanha(cA[j]);
                float iB = siga(vI.y + fmaf(wiB[0], xv, bsB[0]));
                float fB = siga(vF.y + fmaf(wiB[1], xv, bsB[1]));
                float gB = tanha(vG.y + fmaf(wiB[2], xv, bsB[2]));
                float oB = siga(vO.y + fmaf(wiB[3], xv, bsB[3]));
                cB[j] = fmaf(fB, cB[j], iB * gB);
                float hB = oB * tanha(cB[j]);
                u32 pk = f2h2(hA, hB);
                u32 off = nxt * HBUF + (u32)b * HROW + kbyte;
                stc_u32(rb[0] + off, pk); stc_u32(rb[1] + off, pk);
                stc_u32(rb[2] + off, pk); stc_u32(rb[3] + off, pk);
            }
        }
        CSYNC();

        // ===== output: rank r writes batches 4r..4r+3 from its local full h2(t) replica
        if (w < 4) {
            int b = 4 * (int)rank + w;
            const char* hb = smem + OFF_HCAT + nxt * HBUF + (u32)b * HROW + 256u;
            uint2 hv = *(const uint2*)(hb + 8 * lane);
            __half2 h01 = *reinterpret_cast<__half2*>(&hv.x);
            __half2 h23 = *reinterpret_cast<__half2*>(&hv.y);
            float4 wl = *(const float4*)(wlin_s + 4 * lane);
            float p = wl.x * __low2float(h01) + wl.y * __high2float(h01)
                    + wl.z * __low2float(h23) + wl.w * __high2float(h23);
            #pragma unroll
            for (int o = 16; o; o >>= 1)
                p += __shfl_xor_sync(0xffffffffu, p, o);
            if (lane == 0) out[(b0 + b) * SEQL + t] = p + blin;
        }
    }
}

extern "C" void kernel_launch(void* const* d_in, const int* in_sizes, int n_in,
                              void* d_out, int out_size)
{
    static int init = 0;
    if (!init) {
        cudaFuncSetAttribute(lstm_fused_kernel, cudaFuncAttributeMaxDynamicSharedMemorySize, SMEM_TOTAL);
        init = 1;
    }
    lstm_fused_kernel<<<GRID, NT, SMEM_TOTAL>>>(
        (const float*)d_in[0], (const float*)d_in[1], (const float*)d_in[2],
        (const float*)d_in[3], (const float*)d_in[4], (const float*)d_in[5],
        (const float*)d_in[6], (const float*)d_in[7], (const float*)d_in[8],
        (const float*)d_in[9], (const float*)d_in[10], (float*)d_out);
}